// round 14
// baseline (speedup 1.0000x reference)
#include <cuda_runtime.h>
#include <cuda_fp16.h>

#define B_DIM 128
#define N_DIM 131072

constexpr int THREADS  = 256;
constexpr int PAIRS    = 4;                             // pairs of float4 iters per thread (K1)
constexpr int CHUNK    = THREADS * 8 * PAIRS;           // 8192 elements per K1 block
constexpr int BLOCKS_X = N_DIM / CHUNK;                 // 16 K1 blocks per row

constexpr int K2_THREADS = 128;
constexpr int K2_VEC     = 8;                           // uint4 per K2 thread (MLP=8)

// fp16 scratch for unnormalized weights (32 MB; device global, no allocation).
// PERMUTED layout: within each 8192-element chunk, K1 thread t / pair j packs
// the 8 halves of float4-offsets (2j*T+t) and ((2j+1)*T+t) into the uint4 at
// packed index j*T+t (T=256). K2 inverts the map. Row sums come from fp32
// values BEFORE quantization (2.1e-4 norm rel_err vs 1e-3 threshold).
__device__ __half g_scratch_w[(size_t)B_DIM * N_DIM];
// One partial sum per K1 block — rewritten every launch, no zeroing needed.
__device__ float  g_partial[B_DIM * BLOCKS_X];

__device__ __forceinline__ unsigned int h2_bits(__half2 h)
{
    return *reinterpret_cast<unsigned int*>(&h);
}

__device__ __forceinline__ float transition_likelihood(
    float x, float nz, float cterm, float ob, float pwv, float& w_out)
{
    // UNGM transition: x/2 + 25*x/(x^2+1) + 8*cos(1.2*t) + noise*sqrt(10)
    float mean = fmaf(x, 0.5f, 25.0f * __fdividef(x, fmaf(x, x, 1.0f))) + cterm;
    float np   = fmaf(nz, 3.16227766f, mean);
    float om   = np * np * 0.05f;                       // np^2 / 20
    float d    = ob - om;
    float lp   = fmaf(-0.5f * d, d, -0.9189385332f);    // -0.5*log(2*pi)
    w_out      = pwv * __expf(lp);
    return np;
}

__global__ void __launch_bounds__(THREADS)
pf_step_kernel(const float* __restrict__ particles,
               const float* __restrict__ pw,
               const float* __restrict__ obs,
               const float* __restrict__ noise,
               const int*   __restrict__ tstep,
               float* __restrict__ out_np)
{
    const int  b    = blockIdx.y;
    const long base = (long)b * N_DIM + (long)blockIdx.x * CHUNK;

    const float t     = (float)__ldg(tstep);
    const float cterm = 8.0f * cosf(1.2f * t);
    const float ob    = __ldg(obs + b);

    const float4* p4  = (const float4*)(particles + base);
    const float4* n4  = (const float4*)(noise + base);
    const float4* w4  = (const float4*)(pw + base);
    float4* onp4      = (float4*)(out_np + base);
    uint4*  sq4       = (uint4*)(g_scratch_w + base);   // packed scratch view

    float lsum = 0.0f;

    // Two groups of two pairs; within each group ALL 12 LDG.128 issue before
    // any compute/store (192 B in flight per thread).
    #pragma unroll
    for (int g = 0; g < 2; g++) {
        const int j0 = 2 * g;
        float4 X[4], NZ[4], PV[4];

        #pragma unroll
        for (int k = 0; k < 2; k++) {
            const int offa = (2 * (j0 + k)) * THREADS + threadIdx.x;
            X [2*k]   = __ldcs(p4 + offa);
            X [2*k+1] = __ldcs(p4 + offa + THREADS);
            NZ[2*k]   = __ldcs(n4 + offa);
            NZ[2*k+1] = __ldcs(n4 + offa + THREADS);
            PV[2*k]   = __ldcs(w4 + offa);
            PV[2*k+1] = __ldcs(w4 + offa + THREADS);
        }

        #pragma unroll
        for (int k = 0; k < 2; k++) {
            const int j    = j0 + k;
            const int offa = (2 * j) * THREADS + threadIdx.x;
            const int offb = offa + THREADS;
            float4 &xa = X[2*k],  &xb = X[2*k+1];
            float4 &za = NZ[2*k], &zb = NZ[2*k+1];
            float4 &va = PV[2*k], &vb = PV[2*k+1];

            float4 npa, npb, wa, wb;
            npa.x = transition_likelihood(xa.x, za.x, cterm, ob, va.x, wa.x);
            npa.y = transition_likelihood(xa.y, za.y, cterm, ob, va.y, wa.y);
            npa.z = transition_likelihood(xa.z, za.z, cterm, ob, va.z, wa.z);
            npa.w = transition_likelihood(xa.w, za.w, cterm, ob, va.w, wa.w);
            npb.x = transition_likelihood(xb.x, zb.x, cterm, ob, vb.x, wb.x);
            npb.y = transition_likelihood(xb.y, zb.y, cterm, ob, vb.y, wb.y);
            npb.z = transition_likelihood(xb.z, zb.z, cterm, ob, vb.z, wb.z);
            npb.w = transition_likelihood(xb.w, zb.w, cterm, ob, vb.w, wb.w);

            __stcs(onp4 + offa, npa);
            __stcs(onp4 + offb, npb);

            uint4 pk;
            pk.x = h2_bits(__floats2half2_rn(wa.x, wa.y));
            pk.y = h2_bits(__floats2half2_rn(wa.z, wa.w));
            pk.z = h2_bits(__floats2half2_rn(wb.x, wb.y));
            pk.w = h2_bits(__floats2half2_rn(wb.z, wb.w));
            sq4[j * THREADS + threadIdx.x] = pk;        // STG.128, write-back -> L2

            lsum += ((wa.x + wa.y) + (wa.z + wa.w)) + ((wb.x + wb.y) + (wb.z + wb.w));
        }
    }

    // Block reduction -> one partial per block (no atomics, no zero pass)
    __shared__ float red[THREADS / 32];
    #pragma unroll
    for (int s = 16; s > 0; s >>= 1)
        lsum += __shfl_xor_sync(0xFFFFFFFFu, lsum, s);
    const int lane = threadIdx.x & 31;
    const int wid  = threadIdx.x >> 5;
    if (lane == 0) red[wid] = lsum;
    __syncthreads();
    if (wid == 0) {
        float v = (lane < THREADS / 32) ? red[lane] : 0.0f;
        #pragma unroll
        for (int s = 4; s > 0; s >>= 1)
            v += __shfl_xor_sync(0xFFFFFFFFu, v, s);
        if (lane == 0)
            g_partial[b * BLOCKS_X + blockIdx.x] = v;
    }
}

__global__ void __launch_bounds__(K2_THREADS, 10)
normalize_kernel(float* __restrict__ out_w)
{
    const int b = blockIdx.y;

    // Row sum from the 16 per-block partials: 4 vectorized broadcast loads.
    const float4* gp4 = (const float4*)&g_partial[b * BLOCKS_X];
    float rsum = 0.0f;
    #pragma unroll
    for (int j = 0; j < BLOCKS_X / 4; j++) {
        float4 p = __ldg(gp4 + j);
        rsum += (p.x + p.y) + (p.z + p.w);
    }
    const float inv = __frcp_rn(rsum);

    // One K2 block = one K1 chunk. Front-batch all 8 LDG.128 (128 B in
    // flight per thread), then convert/scale/store.
    const long base  = (long)b * N_DIM + (long)blockIdx.x * CHUNK;
    const uint4* sq4 = (const uint4*)(g_scratch_w + base);
    float4* ow4      = (float4*)(out_w + base);

    uint4 q[K2_VEC];
    #pragma unroll
    for (int i = 0; i < K2_VEC; i++)
        q[i] = __ldcs(sq4 + i * K2_THREADS + threadIdx.x);

    #pragma unroll
    for (int i = 0; i < K2_VEC; i++) {
        // Invert the permuted layout: p = j*256 + t1 (j = K1 pair, t1 = K1 tid)
        const int p_idx = i * K2_THREADS + threadIdx.x;
        const int j     = p_idx >> 8;
        const int t1    = p_idx & 255;
        const int offa  = (2 * j) * 256 + t1;           // float4 offset in chunk
        const int offb  = offa + 256;

        float2 f0 = __half22float2(*(__half2*)&q[i].x);
        float2 f1 = __half22float2(*(__half2*)&q[i].y);
        float2 f2 = __half22float2(*(__half2*)&q[i].z);
        float2 f3 = __half22float2(*(__half2*)&q[i].w);

        float4 a, c;
        a.x = f0.x * inv; a.y = f0.y * inv; a.z = f1.x * inv; a.w = f1.y * inv;
        c.x = f2.x * inv; c.y = f2.y * inv; c.z = f3.x * inv; c.w = f3.y * inv;

        __stcs(ow4 + offa, a);
        __stcs(ow4 + offb, c);
    }
}

extern "C" void kernel_launch(void* const* d_in, const int* in_sizes, int n_in,
                              void* d_out, int out_size)
{
    const float* particles = (const float*)d_in[0];   // [B, N, 1]
    const float* pw        = (const float*)d_in[1];   // [B, N]
    const float* obs       = (const float*)d_in[2];   // [B, 1]
    const float* noise     = (const float*)d_in[3];   // [B, N, 1]
    // d_in[4] = uniforms — dead in the reference (resample output unused)
    const int*   tstep     = (const int*)d_in[5];     // scalar

    float* out_np = (float*)d_out;                    // [B, N, 1]
    float* out_w  = out_np + (size_t)B_DIM * N_DIM;   // [B, N]

    dim3 grid1(BLOCKS_X, B_DIM);                      // 16 x 128, 256 thr
    dim3 grid2(BLOCKS_X, B_DIM);                      // 16 x 128, 128 thr

    pf_step_kernel<<<grid1, THREADS>>>(particles, pw, obs, noise, tstep, out_np);
    normalize_kernel<<<grid2, K2_THREADS>>>(out_w);
}

// round 15
// speedup vs baseline: 1.0196x; 1.0196x over previous
#include <cuda_runtime.h>
#include <cuda_fp16.h>

#define B_DIM 128
#define N_DIM 131072

constexpr int THREADS  = 256;
constexpr int PAIRS    = 4;                             // pairs of float4 iters per thread (K1)
constexpr int CHUNK    = THREADS * 8 * PAIRS;           // 8192 elements per K1 block
constexpr int BLOCKS_X = N_DIM / CHUNK;                 // 16 K1 blocks per row

constexpr int K2_THREADS = 128;
constexpr int K2_VEC     = 8;                           // uint4 per K2 thread (MLP=8)

// fp16 scratch for unnormalized weights (32 MB; device global, no allocation).
// PERMUTED layout: within each 8192-element chunk, K1 thread t / pair j packs
// the 8 halves of float4-offsets (2j*T+t) and ((2j+1)*T+t) into the uint4 at
// packed index j*T+t (T=256). K2 inverts the map. Row sums come from fp32
// values BEFORE quantization (2.1e-4 norm rel_err vs 1e-3 threshold).
__device__ __half g_scratch_w[(size_t)B_DIM * N_DIM];
// One partial sum per K1 block — rewritten every launch, no zeroing needed.
__device__ float  g_partial[B_DIM * BLOCKS_X];

__device__ __forceinline__ unsigned int h2_bits(__half2 h)
{
    return *reinterpret_cast<unsigned int*>(&h);
}

__device__ __forceinline__ float transition_likelihood(
    float x, float nz, float cterm, float ob, float pwv, float& w_out)
{
    // UNGM transition: x/2 + 25*x/(x^2+1) + 8*cos(1.2*t) + noise*sqrt(10)
    float mean = fmaf(x, 0.5f, 25.0f * __fdividef(x, fmaf(x, x, 1.0f))) + cterm;
    float np   = fmaf(nz, 3.16227766f, mean);
    float om   = np * np * 0.05f;                       // np^2 / 20
    float d    = ob - om;
    float lp   = fmaf(-0.5f * d, d, -0.9189385332f);    // -0.5*log(2*pi)
    w_out      = pwv * __expf(lp);
    return np;
}

__global__ void __launch_bounds__(THREADS)
pf_step_kernel(const float* __restrict__ particles,
               const float* __restrict__ pw,
               const float* __restrict__ obs,
               const float* __restrict__ noise,
               const int*   __restrict__ tstep,
               float* __restrict__ out_np)
{
    const int  b    = blockIdx.y;
    const long base = (long)b * N_DIM + (long)blockIdx.x * CHUNK;

    const float t     = (float)__ldg(tstep);
    const float cterm = 8.0f * cosf(1.2f * t);
    const float ob    = __ldg(obs + b);

    const float4* p4  = (const float4*)(particles + base);
    const float4* n4  = (const float4*)(noise + base);
    const float4* w4  = (const float4*)(pw + base);
    float4* onp4      = (float4*)(out_np + base);
    uint4*  sq4       = (uint4*)(g_scratch_w + base);   // packed scratch view

    float lsum = 0.0f;

    // Two groups of two pairs; within each group ALL 12 LDG.128 issue before
    // any compute/store (192 B in flight per thread).
    #pragma unroll
    for (int g = 0; g < 2; g++) {
        const int j0 = 2 * g;
        float4 X[4], NZ[4], PV[4];

        #pragma unroll
        for (int k = 0; k < 2; k++) {
            const int offa = (2 * (j0 + k)) * THREADS + threadIdx.x;
            X [2*k]   = __ldcs(p4 + offa);
            X [2*k+1] = __ldcs(p4 + offa + THREADS);
            NZ[2*k]   = __ldcs(n4 + offa);
            NZ[2*k+1] = __ldcs(n4 + offa + THREADS);
            PV[2*k]   = __ldcs(w4 + offa);
            PV[2*k+1] = __ldcs(w4 + offa + THREADS);
        }

        #pragma unroll
        for (int k = 0; k < 2; k++) {
            const int j    = j0 + k;
            const int offa = (2 * j) * THREADS + threadIdx.x;
            const int offb = offa + THREADS;
            float4 &xa = X[2*k],  &xb = X[2*k+1];
            float4 &za = NZ[2*k], &zb = NZ[2*k+1];
            float4 &va = PV[2*k], &vb = PV[2*k+1];

            float4 npa, npb, wa, wb;
            npa.x = transition_likelihood(xa.x, za.x, cterm, ob, va.x, wa.x);
            npa.y = transition_likelihood(xa.y, za.y, cterm, ob, va.y, wa.y);
            npa.z = transition_likelihood(xa.z, za.z, cterm, ob, va.z, wa.z);
            npa.w = transition_likelihood(xa.w, za.w, cterm, ob, va.w, wa.w);
            npb.x = transition_likelihood(xb.x, zb.x, cterm, ob, vb.x, wb.x);
            npb.y = transition_likelihood(xb.y, zb.y, cterm, ob, vb.y, wb.y);
            npb.z = transition_likelihood(xb.z, zb.z, cterm, ob, vb.z, wb.z);
            npb.w = transition_likelihood(xb.w, zb.w, cterm, ob, vb.w, wb.w);

            __stcs(onp4 + offa, npa);
            __stcs(onp4 + offb, npb);

            uint4 pk;
            pk.x = h2_bits(__floats2half2_rn(wa.x, wa.y));
            pk.y = h2_bits(__floats2half2_rn(wa.z, wa.w));
            pk.z = h2_bits(__floats2half2_rn(wb.x, wb.y));
            pk.w = h2_bits(__floats2half2_rn(wb.z, wb.w));
            sq4[j * THREADS + threadIdx.x] = pk;        // STG.128, write-back -> L2

            lsum += ((wa.x + wa.y) + (wa.z + wa.w)) + ((wb.x + wb.y) + (wb.z + wb.w));
        }
    }

    // Block reduction -> one partial per block (no atomics, no zero pass)
    __shared__ float red[THREADS / 32];
    #pragma unroll
    for (int s = 16; s > 0; s >>= 1)
        lsum += __shfl_xor_sync(0xFFFFFFFFu, lsum, s);
    const int lane = threadIdx.x & 31;
    const int wid  = threadIdx.x >> 5;
    if (lane == 0) red[wid] = lsum;
    __syncthreads();
    if (wid == 0) {
        float v = (lane < THREADS / 32) ? red[lane] : 0.0f;
        #pragma unroll
        for (int s = 4; s > 0; s >>= 1)
            v += __shfl_xor_sync(0xFFFFFFFFu, v, s);
        if (lane == 0)
            g_partial[b * BLOCKS_X + blockIdx.x] = v;
    }
}

__global__ void __launch_bounds__(K2_THREADS)
normalize_kernel(float* __restrict__ out_w)
{
    const int b = blockIdx.y;

    const long base  = (long)b * N_DIM + (long)blockIdx.x * CHUNK;
    const uint4* sq4 = (const uint4*)(g_scratch_w + base);
    float4* ow4      = (float4*)(out_w + base);

    // Issue the 8 bulk LDG.128 FIRST (128 B in flight per thread) so they get
    // L1tex queue priority; the broadcast partial loads overlap them.
    uint4 q[K2_VEC];
    #pragma unroll
    for (int i = 0; i < K2_VEC; i++)
        q[i] = __ldcs(sq4 + i * K2_THREADS + threadIdx.x);

    // Row sum from the 16 per-block partials: 4 vectorized broadcast loads.
    const float4* gp4 = (const float4*)&g_partial[b * BLOCKS_X];
    float rsum = 0.0f;
    #pragma unroll
    for (int j = 0; j < BLOCKS_X / 4; j++) {
        float4 p = __ldg(gp4 + j);
        rsum += (p.x + p.y) + (p.z + p.w);
    }
    const float inv = __frcp_rn(rsum);

    #pragma unroll
    for (int i = 0; i < K2_VEC; i++) {
        // Invert the permuted layout: p = j*256 + t1 (j = K1 pair, t1 = K1 tid)
        const int p_idx = i * K2_THREADS + threadIdx.x;
        const int j     = p_idx >> 8;
        const int t1    = p_idx & 255;
        const int offa  = (2 * j) * 256 + t1;           // float4 offset in chunk
        const int offb  = offa + 256;

        float2 f0 = __half22float2(*(__half2*)&q[i].x);
        float2 f1 = __half22float2(*(__half2*)&q[i].y);
        float2 f2 = __half22float2(*(__half2*)&q[i].z);
        float2 f3 = __half22float2(*(__half2*)&q[i].w);

        float4 a, c;
        a.x = f0.x * inv; a.y = f0.y * inv; a.z = f1.x * inv; a.w = f1.y * inv;
        c.x = f2.x * inv; c.y = f2.y * inv; c.z = f3.x * inv; c.w = f3.y * inv;

        __stcs(ow4 + offa, a);
        __stcs(ow4 + offb, c);
    }
}

extern "C" void kernel_launch(void* const* d_in, const int* in_sizes, int n_in,
                              void* d_out, int out_size)
{
    const float* particles = (const float*)d_in[0];   // [B, N, 1]
    const float* pw        = (const float*)d_in[1];   // [B, N]
    const float* obs       = (const float*)d_in[2];   // [B, 1]
    const float* noise     = (const float*)d_in[3];   // [B, N, 1]
    // d_in[4] = uniforms — dead in the reference (resample output unused)
    const int*   tstep     = (const int*)d_in[5];     // scalar

    float* out_np = (float*)d_out;                    // [B, N, 1]
    float* out_w  = out_np + (size_t)B_DIM * N_DIM;   // [B, N]

    dim3 grid1(BLOCKS_X, B_DIM);                      // 16 x 128, 256 thr
    dim3 grid2(BLOCKS_X, B_DIM);                      // 16 x 128, 128 thr

    pf_step_kernel<<<grid1, THREADS>>>(particles, pw, obs, noise, tstep, out_np);
    normalize_kernel<<<grid2, K2_THREADS>>>(out_w);
}